// round 1
// baseline (speedup 1.0000x reference)
#include <cuda_runtime.h>
#include <cuda_bf16.h>

// URPE: out[b,h,i,j] = attention_probs[b,h,i,j] * toe[h,i,j]
// where toe[h,i,j] = w[h, L + j - i] if j >= i else w[h, i - j].
//
// B=2, H=16, L=2048. Pure streaming multiply: 512 MB read + 512 MB write,
// weight table (H * 2L floats = 256 KB) is L2-resident and reused heavily.

static constexpr int LDIM = 2048;
static constexpr int HDIM = 16;
static constexpr int BDIM = 2;
static constexpr int VEC_PER_ROW = LDIM / 4;           // 512 float4 per row
static constexpr long long NVEC =
    (long long)BDIM * HDIM * LDIM * LDIM / 4;          // 33,554,432

__global__ __launch_bounds__(256)
void urpe_mul_kernel(const float4* __restrict__ probs,
                     const float*  __restrict__ w,
                     float4*       __restrict__ out) {
    unsigned int vid = blockIdx.x * blockDim.x + threadIdx.x;
    // Grid exactly covers NVEC (NVEC is a multiple of 256), no bounds check needed,
    // but keep one for safety against grid rounding.
    if (vid >= (unsigned int)NVEC) return;

    // Decode (h, i, j0) from linear float4 index.
    // vecs per (b,h) slab = L*L/4 = 2^20; vecs per row = 2^9.
    int j0 = (vid & (VEC_PER_ROW - 1)) << 2;   // starting j of this float4
    int i  = (vid >> 9)  & (LDIM - 1);
    int h  = (vid >> 20) & (HDIM - 1);

    const float* __restrict__ wh = w + h * (2 * LDIM);

    float4 v = probs[vid];

    int d = j0 - i;  // ranges [-2047, 2047]; d, d+1, d+2, d+3 for the 4 lanes
    // off = (d >= 0) ? L + d : -d   — branchless select, no divergence cost
    int d0 = d,     o0 = (d0 >= 0) ? (LDIM + d0) : -d0;
    int d1 = d + 1, o1 = (d1 >= 0) ? (LDIM + d1) : -d1;
    int d2 = d + 2, o2 = (d2 >= 0) ? (LDIM + d2) : -d2;
    int d3 = d + 3, o3 = (d3 >= 0) ? (LDIM + d3) : -d3;

    v.x *= __ldg(wh + o0);
    v.y *= __ldg(wh + o1);
    v.z *= __ldg(wh + o2);
    v.w *= __ldg(wh + o3);

    out[vid] = v;
}

extern "C" void kernel_launch(void* const* d_in, const int* in_sizes, int n_in,
                              void* d_out, int out_size) {
    const float4* probs = (const float4*)d_in[0];   // attention_probs [B,H,L,L] f32
    const float*  w     = (const float*)d_in[1];    // urpe_weight_    [H,2L]   f32
    float4*       out   = (float4*)d_out;

    const int threads = 256;
    const int blocks  = (int)(NVEC / threads);      // 131072, exact
    urpe_mul_kernel<<<blocks, threads>>>(probs, w, out);
}

// round 2
// speedup vs baseline: 1.0652x; 1.0652x over previous
#include <cuda_runtime.h>
#include <cuda_bf16.h>

// URPE: out[b,h,i,j] = attention_probs[b,h,i,j] * toe[h,i,j]
// toe[h,i,j] = w[h, L + j - i] if j >= i else w[h, i - j].
//
// B=2, H=16, L=2048. HBM-bound streaming multiply (512 MB in + 512 MB out).
// R1: ILP=4 per thread with front-batched stream loads (raise MLP_p1),
// streaming cache hints on the 1GB stream, __ldg on the L2-resident weights.

static constexpr int LDIM = 2048;
static constexpr int HDIM = 16;
static constexpr int BDIM = 2;
static constexpr int VEC_PER_ROW = LDIM / 4;            // 512 float4 per row
static constexpr long long NVEC =
    (long long)BDIM * HDIM * LDIM * LDIM / 4;           // 33,554,432
static constexpr int THREADS = 256;
static constexpr int ILP = 4;                           // float4s per thread

__global__ __launch_bounds__(THREADS)
void urpe_mul_kernel(const float4* __restrict__ probs,
                     const float*  __restrict__ w,
                     float4*       __restrict__ out) {
    // Block covers ILP*THREADS = 1024 consecutive float4 (2 full rows).
    // Thread t owns vids base, base+256, base+512, base+768 — each wave coalesced.
    unsigned int base = blockIdx.x * (THREADS * ILP) + threadIdx.x;

    // Phase 1: front-batch all stream loads (4 independent LDG.128.CS in flight).
    float4 v[ILP];
#pragma unroll
    for (int k = 0; k < ILP; k++) {
        v[k] = __ldcs(&probs[base + k * THREADS]);
    }

    // Phase 2: weight gather + multiply (weights are L1/L2-hot, 256 KB total).
#pragma unroll
    for (int k = 0; k < ILP; k++) {
        unsigned int vid = base + k * THREADS;
        int j0 = (vid & (VEC_PER_ROW - 1)) << 2;
        int i  = (vid >> 9)  & (LDIM - 1);
        int h  = (vid >> 20) & (HDIM - 1);
        const float* __restrict__ wh = w + h * (2 * LDIM);

        int d = j0 - i;
        int d0 = d,     o0 = (d0 >= 0) ? (LDIM + d0) : -d0;
        int d1 = d + 1, o1 = (d1 >= 0) ? (LDIM + d1) : -d1;
        int d2 = d + 2, o2 = (d2 >= 0) ? (LDIM + d2) : -d2;
        int d3 = d + 3, o3 = (d3 >= 0) ? (LDIM + d3) : -d3;

        v[k].x *= __ldg(wh + o0);
        v[k].y *= __ldg(wh + o1);
        v[k].z *= __ldg(wh + o2);
        v[k].w *= __ldg(wh + o3);
    }

    // Phase 3: streaming stores.
#pragma unroll
    for (int k = 0; k < ILP; k++) {
        __stcs(&out[base + k * THREADS], v[k]);
    }
}

extern "C" void kernel_launch(void* const* d_in, const int* in_sizes, int n_in,
                              void* d_out, int out_size) {
    const float4* probs = (const float4*)d_in[0];   // attention_probs [B,H,L,L] f32
    const float*  w     = (const float*)d_in[1];    // urpe_weight_    [H,2L]   f32
    float4*       out   = (float4*)d_out;

    const int blocks = (int)(NVEC / (THREADS * ILP));  // 32768, exact
    urpe_mul_kernel<<<blocks, THREADS>>>(probs, w, out);
}